// round 17
// baseline (speedup 1.0000x reference)
#include <cuda_runtime.h>
#include <cuda_bf16.h>
#include <cstdint>

// Problem constants
#define BB      32
#define CC      256
#define HW      1024
#define NTOT    32768          // BB*HW
#define KK      1024
#define NQ      8388608        // BB*CC*HW
#define MARGINA 2e-4f          // margin in a-space (a = dot - wn/2; s = -2a; 2e-4 == 4e-4 in s)

typedef unsigned long long u64;

// Scratch (static device globals only — no runtime alloc)
__device__ double   g_loss;
__device__ int      g_idx[NTOT];
__device__ float    g_wnorm[KK];
__device__ float    g_zn2[NTOT];
__device__ uint4    g_wpackA[32768];     // [nbG 128][ks2 8][lane 32] paired B frags (512KB)
__device__ uint32_t g_wpackW[4096];      // [nbG 128][lane 32] wn-step B frag (16KB)
__device__ int      g_cand[NTOT * 8];    // candidate ks for status-1 tokens
__device__ int      g_stat[NTOT];        // 0=done, 1=rescore cands, 2=full scan

// ---------------------------------------------------------------------------
// Kernel 1: ||w_k||^2 — warp per row (coalesced), double reduce + loss init
// ---------------------------------------------------------------------------
__global__ void wnorm_kernel(const float* __restrict__ w) {
    const int k    = blockIdx.x * 8 + (threadIdx.x >> 5);
    const int lane = threadIdx.x & 31;
    if (blockIdx.x == 0 && threadIdx.x == 0) g_loss = 0.0;
    const float* row = w + (size_t)k * CC;
    double s = 0.0;
    #pragma unroll
    for (int i = 0; i < CC / 32; i++) {
        double v = (double)row[lane + i * 32];
        s += v * v;
    }
    #pragma unroll
    for (int o = 16; o; o >>= 1) s += __shfl_xor_sync(0xffffffffu, s, o);
    if (lane == 0) g_wnorm[k] = (float)s;
}

// ---------------------------------------------------------------------------
// Kernel 2: zn2 — exact XLA row-reduce emulation. DO NOT CHANGE (rel_err 0.0).
// ---------------------------------------------------------------------------
__global__ void zn2_kernel(const float* __restrict__ z) {
    const int n  = blockIdx.x * 256 + threadIdx.x;
    const int b  = n >> 10;
    const int hw = n & (HW - 1);
    const float* row = z + (size_t)b * (CC * HW) + hw;
    float W[4];
    #pragma unroll
    for (int w4 = 0; w4 < 4; w4++) {
        float p[32];
        #pragma unroll
        for (int l = 0; l < 32; l++) {
            float a = row[(size_t)(64 * w4 + 2 * l) * HW];
            float c = row[(size_t)(64 * w4 + 2 * l + 1) * HW];
            p[l] = __fadd_rn(__fmul_rn(a, a), __fmul_rn(c, c));
        }
        #pragma unroll
        for (int off = 16; off >= 1; off >>= 1)
            #pragma unroll
            for (int l = 0; l < 16; l++)
                if (l < off) p[l] = __fadd_rn(p[l], p[l + off]);
        W[w4] = p[0];
    }
    g_zn2[n] = __fadd_rn(__fadd_rn(W[0], W[2]), __fadd_rn(W[1], W[3]));
}

// ---------------------------------------------------------------------------
// Kernel 3: pack w into paired B-fragment order + wn-step frags.
// Paired: [nbG][ks2][lane] uint4 = frags for ks=2*ks2 (x,y) and ks=2*ks2+1 (z,w).
// wn-step: B[k-slot 0][code] = bf16(-wn/2)  (lane c4==0 holds it in reg0.lo).
// MUST run after wnorm_kernel.
// ---------------------------------------------------------------------------
__global__ void wpack_kernel(const float* __restrict__ w) {
    const int idx = blockIdx.x * 256 + threadIdx.x;   // 0..32767
    const int lane = idx & 31, ks2 = (idx >> 5) & 7, nbG = idx >> 8;
    const int code = nbG * 8 + (lane >> 2);
    const int c = lane & 3;
    const float* wr = w + (size_t)code * CC;
    const int d0 = (2 * ks2) * 16 + 2 * c;
    const int d1 = (2 * ks2 + 1) * 16 + 2 * c;
    __nv_bfloat162 r0 = __floats2bfloat162_rn(wr[d0],      wr[d0 + 1]);
    __nv_bfloat162 r1 = __floats2bfloat162_rn(wr[d0 + 8],  wr[d0 + 9]);
    __nv_bfloat162 r2 = __floats2bfloat162_rn(wr[d1],      wr[d1 + 1]);
    __nv_bfloat162 r3 = __floats2bfloat162_rn(wr[d1 + 8],  wr[d1 + 9]);
    g_wpackA[idx] = make_uint4(*(uint32_t*)&r0, *(uint32_t*)&r1,
                               *(uint32_t*)&r2, *(uint32_t*)&r3);

    if (idx < 4096) {
        const int l2 = idx & 31, nb2 = idx >> 5;
        const int code2 = nb2 * 8 + (l2 >> 2);
        uint32_t bw = 0;
        if ((l2 & 3) == 0) {
            __nv_bfloat162 v = __floats2bfloat162_rn(-0.5f * g_wnorm[code2], 0.f);
            bw = *(uint32_t*)&v;
        }
        g_wpackW[idx] = bw;
    }
}

// ---------------------------------------------------------------------------
// Kernel 4: bf16 mma.sync argmin v4 — wn folded into GEMM (17th k-step),
// paired B LDS.128, argMAX of acc = dot - wn/2. 256 thr / 8 warps, 16 tok/warp.
// Smem (u32): apack [0,16384) | bstage uint4 [16384,24576) | bwn [24576,24832)
// ---------------------------------------------------------------------------
#define UPDMAX(h, s, k) do { \
    if ((s) > v1[h]) { v3[h] = v2[h]; v2[h] = v1[h]; k2[h] = k1[h]; \
        v1[h] = (s); k1[h] = (k); } \
    else if ((s) > v2[h]) { v3[h] = v2[h]; v2[h] = (s); k2[h] = (k); } \
    else if ((s) > v3[h]) { v3[h] = (s); } \
} while (0)

#define MMA_BF16(C, A, b0, b1) \
    asm volatile("mma.sync.aligned.m16n8k16.row.col.f32.bf16.bf16.f32 " \
        "{%0,%1,%2,%3}, {%4,%5,%6,%7}, {%8,%9}, {%0,%1,%2,%3};" \
        : "+f"((C)[0]), "+f"((C)[1]), "+f"((C)[2]), "+f"((C)[3]) \
        : "r"((A).x), "r"((A).y), "r"((A).z), "r"((A).w), "r"(b0), "r"(b1))

__global__ __launch_bounds__(256, 2)
void mma_argmin_kernel(const float* __restrict__ z, const float* __restrict__ w) {
    extern __shared__ uint32_t smu[];
    uint32_t* apack  = smu;                       // 16384 u32 (64KB)
    uint4*    bs4    = (uint4*)(smu + 16384);     // 2048 uint4 (32KB)
    uint32_t* bwn    = smu + 24576;               // 256 u32 (1KB)
    float*    stage  = (float*)(smu + 16384);     // 4096 f (A-pack phase only)

    const int t = threadIdx.x, wp = t >> 5, lane = t & 31;
    const int c4 = lane & 3;
    const int n0  = blockIdx.x * 128;
    const int b   = blockIdx.x >> 3;
    const int hw0 = (blockIdx.x & 7) * 128;
    const float* zb = z + (size_t)b * (CC * HW) + hw0;

    // ---- pack A (z rows) into fragment-ordered bf16 smem, 32-d chunks ----
    for (int cd = 0; cd < 8; cd++) {
        __syncthreads();
        #pragma unroll
        for (int j = 0; j < 4; j++) {
            int fi = j * 256 + t;                 // 1024 float4 chunks
            int dl = fi >> 5, h4 = fi & 31;
            *(float4*)&stage[dl * 128 + h4 * 4] =
                *(const float4*)&zb[(size_t)(cd * 32 + dl) * HW + h4 * 4];
        }
        __syncthreads();
        #pragma unroll
        for (int i = 0; i < 8; i++) {
            int slot = i * 256 + t;               // 2048 slots
            int ai = slot & 3, tid2 = (slot >> 2) & 31;
            int rp = (slot >> 7) & 1, wp2 = (slot >> 8) & 3, ksl = (slot >> 10) & 1;
            int tok  = wp2 * 32 + rp * 16 + (ai & 1) * 8 + (tid2 >> 2);
            int dloc = ksl * 16 + ((ai >> 1) & 1) * 8 + 2 * (tid2 & 3);
            __nv_bfloat162 v = __floats2bfloat162_rn(stage[dloc * 128 + tok],
                                                     stage[(dloc + 1) * 128 + tok]);
            int ks = cd * 2 + ksl;
            apack[(ks * 8 + wp2 * 2 + rp) * 128 + tid2 * 4 + ai] = *(uint32_t*)&v;
        }
    }

    const uint4* ap4 = (const uint4*)apack;

    // constant A fragment for the wn-step: 1.0 in k-slot 0 (c4==0 lanes)
    uint4 Ac;
    Ac.x = Ac.y = (c4 == 0) ? 0x00003F80u : 0u;
    Ac.z = Ac.w = 0u;

    float v1[2], v2[2], v3[2];
    int   k1[2], k2[2];
    #pragma unroll
    for (int h = 0; h < 2; h++) {
        v1[h] = v2[h] = v3[h] = -1e30f;
        k1[h] = k2[h] = 0x7fffffff;
    }

    for (int nt = 0; nt < 16; nt++) {
        __syncthreads();                          // prev tile consumed
        // ---- stage B tile (32KB + 1KB wn) cooperatively ----
        const uint4* bsrc = g_wpackA + nt * 2048;
        #pragma unroll
        for (int j = 0; j < 8; j++)
            bs4[j * 256 + t] = __ldg(&bsrc[j * 256 + t]);
        bwn[t] = __ldg(&g_wpackW[nt * 256 + t]);
        __syncthreads();

        float acc[8][4];
        #pragma unroll
        for (int nb = 0; nb < 8; nb++)
            #pragma unroll
            for (int r = 0; r < 4; r++) acc[nb][r] = 0.f;

        // A prefetch pipeline; B loaded in-loop from smem (LDS.128 per pair)
        uint4 A_e = ap4[(0 * 8 + wp) * 32 + lane];
        uint4 A_o = ap4[(1 * 8 + wp) * 32 + lane];
        #pragma unroll
        for (int ks2 = 0; ks2 < 8; ks2++) {
            uint4 An_e, An_o;
            if (ks2 < 7) {
                An_e = ap4[((2 * ks2 + 2) * 8 + wp) * 32 + lane];
                An_o = ap4[((2 * ks2 + 3) * 8 + wp) * 32 + lane];
            }
            #pragma unroll
            for (int nb = 0; nb < 8; nb++) {
                uint4 Bq = bs4[(nb * 8 + ks2) * 32 + lane];
                MMA_BF16(acc[nb], A_e, Bq.x, Bq.y);
                MMA_BF16(acc[nb], A_o, Bq.z, Bq.w);
            }
            if (ks2 < 7) { A_e = An_e; A_o = An_o; }
        }
        // wn-step: acc += 1.0 * (-wn/2)
        #pragma unroll
        for (int nb = 0; nb < 8; nb++) {
            uint32_t bw = bwn[nb * 32 + lane];
            MMA_BF16(acc[nb], Ac, bw, 0u);
        }

        // epilogue: a = dot - wn/2; argMAX tracking (ascending k, strict >)
        #pragma unroll
        for (int nb = 0; nb < 8; nb++) {
            int kb = nt * 64 + nb * 8 + 2 * c4;
            UPDMAX(0, acc[nb][0], kb); UPDMAX(0, acc[nb][1], kb + 1);
            UPDMAX(1, acc[nb][2], kb); UPDMAX(1, acc[nb][3], kb + 1);
        }
    }

    // ---- per token-row: quad-combine, certify or hand off ----
    #pragma unroll
    for (int h = 0; h < 2; h++) {
        float gm = v1[h];
        gm = fmaxf(gm, __shfl_xor_sync(0xffffffffu, gm, 1));
        gm = fmaxf(gm, __shfl_xor_sync(0xffffffffu, gm, 2));
        float thr = gm - MARGINA;
        int c1 = v1[h] >= thr;
        int c2 = v2[h] >= thr;
        int ov = v3[h] >= thr;
        int tot = c1 + c2;
        tot += __shfl_xor_sync(0xffffffffu, tot, 1);
        tot += __shfl_xor_sync(0xffffffffu, tot, 2);
        ov |= __shfl_xor_sync(0xffffffffu, ov, 1);
        ov |= __shfl_xor_sync(0xffffffffu, ov, 2);
        int kw = c1 ? k1[h] : 0x7fffffff;
        kw = min(kw, __shfl_xor_sync(0xffffffffu, kw, 1));
        kw = min(kw, __shfl_xor_sync(0xffffffffu, kw, 2));
        int n  = n0 + wp * 16 + h * 8 + (lane >> 2);
        int st = ov ? 2 : (tot == 1 ? 0 : 1);
        if (st == 1) {
            g_cand[n * 8 + c4 * 2]     = c1 ? k1[h] : -1;
            g_cand[n * 8 + c4 * 2 + 1] = c2 ? k2[h] : -1;
        }
        if (c4 == 0) {
            if (st == 0) g_idx[n] = kw;
            g_stat[n] = st;
        }
    }
}

// ---------------------------------------------------------------------------
// Kernel 5: cleanup — tile-staged exact rescore, float4 w reads (unchanged).
// ---------------------------------------------------------------------------
__global__ __launch_bounds__(128, 1)
void cleanup_kernel(const float* __restrict__ z, const float* __restrict__ w) {
    extern __shared__ float zs[];          // [256][128] fp32 = 128KB
    __shared__ int   s2list[128];
    __shared__ int   s2cnt;
    __shared__ float rv[128];
    __shared__ int   rk[128];

    const int t   = threadIdx.x;
    const int n0  = blockIdx.x * 128;
    const int b   = blockIdx.x >> 3;
    const int hw0 = (blockIdx.x & 7) * 128;
    const float* zb = z + (size_t)b * (CC * HW) + hw0;

    if (t == 0) s2cnt = 0;
    const int st = g_stat[n0 + t];
    if (!__syncthreads_or(st != 0)) return;     // whole tile certified

    #pragma unroll
    for (int j = 0; j < 64; j++) {
        int idx = j * 128 + t;                  // 0..8191 float4 chunks
        int d = idx >> 5, h4 = idx & 31;
        *(float4*)&zs[d * 128 + h4 * 4] = *(const float4*)&zb[(size_t)d * HW + h4 * 4];
    }
    __syncthreads();

    const int n = n0 + t;
    if (st == 1) {
        const float zn2v = g_zn2[n];
        float bv = 1e30f; int bk = 0x7fffffff;
        #pragma unroll
        for (int c = 0; c < 8; c++) {
            int k = g_cand[n * 8 + c];
            if (k < 0) continue;
            const float4* wr4 = (const float4*)(w + (size_t)k * CC);
            float acc = 0.f;
            #pragma unroll 16
            for (int i = 0; i < CC / 4; i++) {
                float4 v = __ldg(&wr4[i]);
                acc = __fmaf_rn(zs[(4 * i + 0) * 128 + t], v.x, acc);
                acc = __fmaf_rn(zs[(4 * i + 1) * 128 + t], v.y, acc);
                acc = __fmaf_rn(zs[(4 * i + 2) * 128 + t], v.z, acc);
                acc = __fmaf_rn(zs[(4 * i + 3) * 128 + t], v.w, acc);
            }
            float d2 = __fadd_rn(__fmaf_rn(-2.f, acc, zn2v), g_wnorm[k]);
            if (d2 < bv || (d2 == bv && k < bk)) { bv = d2; bk = k; }
        }
        g_idx[n] = bk;
    } else if (st == 2) {
        int p = atomicAdd(&s2cnt, 1);
        s2list[p] = t;
    }
    __syncthreads();

    const int cnt = s2cnt;
    for (int i = 0; i < cnt; i++) {
        const int tok = s2list[i];
        const float zn2v = g_zn2[n0 + tok];
        float bv = 1e30f; int bk = 0x7fffffff;
        #pragma unroll
        for (int j = 0; j < 8; j++) {
            int k = t * 8 + j;                   // ascending k per thread
            const float4* wr4 = (const float4*)(w + (size_t)k * CC);
            float acc = 0.f;
            #pragma unroll 16
            for (int i2 = 0; i2 < CC / 4; i2++) {
                float4 v = __ldg(&wr4[i2]);
                acc = __fmaf_rn(zs[(4 * i2 + 0) * 128 + tok], v.x, acc);
                acc = __fmaf_rn(zs[(4 * i2 + 1) * 128 + tok], v.y, acc);
                acc = __fmaf_rn(zs[(4 * i2 + 2) * 128 + tok], v.z, acc);
                acc = __fmaf_rn(zs[(4 * i2 + 3) * 128 + tok], v.w, acc);
            }
            float d2 = __fadd_rn(__fmaf_rn(-2.f, acc, zn2v), g_wnorm[k]);
            if (d2 < bv) { bv = d2; bk = k; }
        }
        rv[t] = bv; rk[t] = bk;
        __syncthreads();
        for (int off = 64; off >= 1; off >>= 1) {
            if (t < off) {
                float ov2 = rv[t + off]; int ok2 = rk[t + off];
                if (ov2 < rv[t] || (ov2 == rv[t] && ok2 < rk[t])) {
                    rv[t] = ov2; rk[t] = ok2;
                }
            }
            __syncthreads();
        }
        if (t == 0) g_idx[n0 + tok] = rk[0];
        __syncthreads();
    }
}

// ---------------------------------------------------------------------------
// Kernel 6: gather — tile-staged. Block = 64 tokens, 256 threads (unchanged).
// ---------------------------------------------------------------------------
__global__ __launch_bounds__(256, 1)
void gather_kernel(const float* __restrict__ z,
                   const float* __restrict__ w,
                   float* __restrict__ out) {
    extern __shared__ float wstg[];               // 64*257 floats
    const int t   = threadIdx.x;
    const int n0  = blockIdx.x * 64;              // 512 blocks
    const int b   = n0 >> 10;
    const int hw0 = n0 & (HW - 1);

    {
        const int wp = t >> 5, lane = t & 31;
        #pragma unroll
        for (int r = 0; r < 8; r++) {
            const int tok = wp * 8 + r;
            const int k = g_idx[n0 + tok];
            const float4* src = (const float4*)(w + (size_t)k * CC);
            #pragma unroll
            for (int j = 0; j < 2; j++) {
                const int i = lane + j * 32;      // 0..63 f4
                float4 v = __ldg(&src[i]);
                float* dst = &wstg[tok * 257 + i * 4];
                dst[0] = v.x; dst[1] = v.y; dst[2] = v.z; dst[3] = v.w;
            }
        }
    }
    __syncthreads();

    const int tok = t & 63;
    const int cq  = t >> 6;
    double s = 0.0;
    #pragma unroll 16
    for (int cc = 0; cc < 64; cc++) {
        const int c = cq * 64 + cc;
        const size_t g = ((size_t)b * CC + c) * HW + hw0 + tok;
        const float v = wstg[tok * 257 + c];
        const float zv = z[g];
        out[g] = v;
        const float d = zv - v;
        s += (double)d * (double)d;
    }
    #pragma unroll
    for (int o = 16; o; o >>= 1) s += __shfl_xor_sync(0xffffffffu, s, o);
    __shared__ double bs[8];
    const int lane = t & 31, wd = t >> 5;
    if (lane == 0) bs[wd] = s;
    __syncthreads();
    if (t == 0) {
        double tot = 0.0;
        #pragma unroll
        for (int i = 0; i < 8; i++) tot += bs[i];
        atomicAdd(&g_loss, tot);
    }
}

__global__ void finalize_kernel(float* __restrict__ out, int out_size) {
    float loss = (float)(g_loss * (1.0 / (double)NQ));
    if (out_size >= NQ + 1) out[NQ] = loss;
    if (out_size >= NQ + 2) out[NQ + 1] = loss;
}

// ---------------------------------------------------------------------------
extern "C" void kernel_launch(void* const* d_in, const int* in_sizes, int n_in,
                              void* d_out, int out_size) {
    const float* z = (const float*)d_in[0];
    const float* w = (const float*)d_in[1];
    float* out = (float*)d_out;

    const int smem_mma = (16384 + 8192 + 256) * 4;    // 99328 B
    const int smem_cln = 256 * 128 * 4;               // 131072 B
    const int smem_gth = 64 * 257 * 4;                // 65792 B
    cudaFuncSetAttribute(mma_argmin_kernel,
                         cudaFuncAttributeMaxDynamicSharedMemorySize, smem_mma);
    cudaFuncSetAttribute(cleanup_kernel,
                         cudaFuncAttributeMaxDynamicSharedMemorySize, smem_cln);
    cudaFuncSetAttribute(gather_kernel,
                         cudaFuncAttributeMaxDynamicSharedMemorySize, smem_gth);

    wnorm_kernel<<<KK / 8, 256>>>(w);                 // must precede wpack
    wpack_kernel<<<128, 256>>>(w);
    zn2_kernel<<<NTOT / 256, 256>>>(z);
    mma_argmin_kernel<<<NTOT / 128, 256, smem_mma>>>(z, w);
    cleanup_kernel<<<NTOT / 128, 128, smem_cln>>>(z, w);
    gather_kernel<<<NTOT / 64, 256, smem_gth>>>(z, w, out);
    finalize_kernel<<<1, 1>>>(out, out_size);
}